// round 4
// baseline (speedup 1.0000x reference)
#include <cuda_runtime.h>
#include <cuda_bf16.h>
#include <stdint.h>

// GCN graph classifier:
//   2x (GCNConv(sym-norm, self-loops) + ReLU) -> global_mean_pool -> Linear
// N=100000 nodes, E=1.6M edges, H=128, G=512 graphs, OUT=2.
//
// Strategy:
//   - deg/dis via float atomics (cheap, E adds)
//   - CSR by counting sort on col (hist + scan + scatter) -> atomic-free
//     node-parallel aggregation (warp per node, float4 lanes, L2-resident gather)
//   - fp32 register-tiled SGEMM (128x128 tile, 8x8 per thread)
//   - pooling: batch is sorted -> block-per-graph register reduction, no atomics
//   - int64 vs int32 index dtype detected on device (JAX x64 may be disabled)

#define HD   128
#define NMAX 100352
#define EMAX 1605632
#define GMX  1024

__device__ __align__(16) float g_dis[NMAX];     // deg accum, then rsqrt(deg)
__device__ __align__(16) float g_selfc[NMAX];   // 1/deg (self-loop coef)
__device__ __align__(16) int   g_row[EMAX];
__device__ __align__(16) int   g_col[EMAX];
__device__ __align__(16) int   g_batch[NMAX];
__device__ __align__(16) int   g_cnt[NMAX];
__device__ __align__(16) int   g_off[NMAX + 1];
__device__ __align__(16) int   g_cur[NMAX];
__device__ __align__(16) int   g_bsum[256];
__device__ __align__(16) int   g_bsumx[256];
__device__ __align__(16) int   g_srow[EMAX];    // CSR source rows
__device__ __align__(16) float g_scoef[EMAX];   // CSR edge coefficients
__device__ __align__(16) float g_xw[(size_t)NMAX * HD];  // GEMM output
__device__ __align__(16) float g_h[(size_t)NMAX * HD];   // layer output
__device__ __align__(16) float g_pool[GMX * HD];
__device__ __align__(16) int   g_gstart[GMX + 1];
__device__ int g_ei64;
__device__ int g_b64;

// --------------------------------------------------------------------------
// dtype detection: if the array is int64, every odd 32-bit word (hi half) is 0.
// edge_index values are uniform in [0,N) -> odd words nonzero w.h.p. if int32.
// batch is sorted ascending from 0, so sample near the END of the first n
// 32-bit words (values ~G-1 there if int32; hi-halves 0 if int64).
// --------------------------------------------------------------------------
__global__ void k_detect(const int* __restrict__ ei32, const int* __restrict__ b32, int n)
{
    if (blockIdx.x != 0 || threadIdx.x != 0) return;
    int a = 1;
    for (int k = 1; k < 256; k += 2) {
        if (ei32[k] != 0) { a = 0; break; }
    }
    g_ei64 = a;
    int b = 1;
    int base = (n > 256) ? ((n - 256) & ~1) : 0;
    for (int k = 1; k < 256; k += 2) {
        int w = base + k;
        if (w < n && b32[w] != 0) { b = 0; break; }
    }
    g_b64 = b;
}

__global__ void k_convert_edges(const void* __restrict__ ei, int e)
{
    int i = blockIdx.x * blockDim.x + threadIdx.x;
    if (i >= e) return;
    if (g_ei64) {
        const long long* p = (const long long*)ei;
        g_row[i] = (int)p[i];
        g_col[i] = (int)p[(size_t)e + i];
    } else {
        const int* p = (const int*)ei;
        g_row[i] = p[i];
        g_col[i] = p[e + i];
    }
}

__global__ void k_convert_batch(const void* __restrict__ b, int n)
{
    int i = blockIdx.x * blockDim.x + threadIdx.x;
    if (i >= n) return;
    g_batch[i] = g_b64 ? (int)((const long long*)b)[i] : ((const int*)b)[i];
}

// --------------------------------------------------------------------------
// degree / normalization
// --------------------------------------------------------------------------
__global__ void k_init(int n)
{
    int i = blockIdx.x * blockDim.x + threadIdx.x;
    if (i < n) { g_dis[i] = 1.0f; g_cnt[i] = 0; }  // self-loop weight 1
}

__global__ void k_edge_accum(const float* __restrict__ ew, int e)
{
    int i = blockIdx.x * blockDim.x + threadIdx.x;
    if (i >= e) return;
    int c = g_col[i];
    atomicAdd(&g_dis[c], ew[i]);
    atomicAdd(&g_cnt[c], 1);
}

__global__ void k_dis(int n)
{
    int i = blockIdx.x * blockDim.x + threadIdx.x;
    if (i >= n) return;
    float d = g_dis[i];          // deg >= 1 (self loop), so rsqrt is safe
    float r = rsqrtf(d);
    g_dis[i] = r;
    g_selfc[i] = r * r;          // dis^2 = 1/deg
}

// --------------------------------------------------------------------------
// exclusive scan of g_cnt -> g_off (3 kernels), then counting-sort scatter
// --------------------------------------------------------------------------
__global__ void k_scan1(int n)
{
    __shared__ int s[1024];
    int i = blockIdx.x * 1024 + threadIdx.x;
    int v = (i < n) ? g_cnt[i] : 0;
    s[threadIdx.x] = v;
    __syncthreads();
    for (int off = 1; off < 1024; off <<= 1) {
        int t = 0;
        if (threadIdx.x >= off) t = s[threadIdx.x - off];
        __syncthreads();
        if (threadIdx.x >= off) s[threadIdx.x] += t;
        __syncthreads();
    }
    if (i < n) g_off[i] = s[threadIdx.x];              // within-block inclusive
    if (threadIdx.x == 1023) g_bsum[blockIdx.x] = s[1023];
}

__global__ void k_scan2(int nb)
{
    __shared__ int s[1024];
    int t = threadIdx.x;
    int v = (t < nb) ? g_bsum[t] : 0;
    s[t] = v;
    __syncthreads();
    for (int off = 1; off < 1024; off <<= 1) {
        int u = 0;
        if (t >= off) u = s[t - off];
        __syncthreads();
        if (t >= off) s[t] += u;
        __syncthreads();
    }
    if (t < nb) g_bsumx[t] = s[t] - v;                 // exclusive block bases
}

__global__ void k_scan3(int n, int e)
{
    int i = blockIdx.x * blockDim.x + threadIdx.x;
    if (i < n) {
        int ex = g_off[i] - g_cnt[i] + g_bsumx[i >> 10];
        g_off[i] = ex;
        g_cur[i] = ex;
    }
    if (i == 0) g_off[n] = e;
}

__global__ void k_scatter(const float* __restrict__ ew, int e)
{
    int i = blockIdx.x * blockDim.x + threadIdx.x;
    if (i >= e) return;
    int r = g_row[i];
    int c = g_col[i];
    float coef = g_dis[r] * ew[i] * g_dis[c];
    int slot = atomicAdd(&g_cur[c], 1);
    g_srow[slot] = r;
    g_scoef[slot] = coef;
}

// --------------------------------------------------------------------------
// SGEMM: C[n x 128] = A[n x 128] @ W[128 x 128], fp32
// block = 256 threads, tile 128 rows x 128 cols, 8x8 per thread, K-chunk 8
// dst is always g_xw; src is either the external input x or g_h (layer 2).
// --------------------------------------------------------------------------
__global__ void __launch_bounds__(256) k_gemm(const float* __restrict__ Xin,
                                              const float* __restrict__ W,
                                              int useH, int n)
{
    __shared__ __align__(16) float As[8][128];  // [k][m]
    __shared__ __align__(16) float Ws[8][128];  // [k][n]

    const float* A = useH ? (const float*)g_h : Xin;
    float* C = g_xw;

    int tid = threadIdx.x;
    int tx = tid & 15;         // col group
    int ty = tid >> 4;         // row group
    int m0 = ty * 8;
    int n0 = tx * 8;
    int rowBase = blockIdx.x * 128;

    float acc[8][8];
#pragma unroll
    for (int i = 0; i < 8; i++)
#pragma unroll
        for (int j = 0; j < 8; j++) acc[i][j] = 0.0f;

    int lr = tid >> 1;                // 0..127 (row within tile for A load)
    int kp = (tid & 1) * 4;           // 0 or 4
    int arow = rowBase + lr;

    for (int kc = 0; kc < HD; kc += 8) {
        float4 av = make_float4(0.f, 0.f, 0.f, 0.f);
        if (arow < n) av = *(const float4*)(A + (size_t)arow * HD + kc + kp);
        As[kp + 0][lr] = av.x;
        As[kp + 1][lr] = av.y;
        As[kp + 2][lr] = av.z;
        As[kp + 3][lr] = av.w;

        int widx = tid * 4;
        int wk = widx >> 7;            // 0..7
        int wn = widx & 127;
        *(float4*)&Ws[wk][wn] = *(const float4*)(W + (size_t)(kc + wk) * HD + wn);
        __syncthreads();

#pragma unroll
        for (int k = 0; k < 8; k++) {
            float a[8], w[8];
            *(float4*)&a[0] = *(const float4*)&As[k][m0];
            *(float4*)&a[4] = *(const float4*)&As[k][m0 + 4];
            *(float4*)&w[0] = *(const float4*)&Ws[k][n0];
            *(float4*)&w[4] = *(const float4*)&Ws[k][n0 + 4];
#pragma unroll
            for (int i = 0; i < 8; i++)
#pragma unroll
                for (int j = 0; j < 8; j++)
                    acc[i][j] += a[i] * w[j];
        }
        __syncthreads();
    }

#pragma unroll
    for (int i = 0; i < 8; i++) {
        int r = rowBase + m0 + i;
        if (r < n) {
            float4 o0 = make_float4(acc[i][0], acc[i][1], acc[i][2], acc[i][3]);
            float4 o1 = make_float4(acc[i][4], acc[i][5], acc[i][6], acc[i][7]);
            *(float4*)(C + (size_t)r * HD + n0)     = o0;
            *(float4*)(C + (size_t)r * HD + n0 + 4) = o1;
        }
    }
}

// --------------------------------------------------------------------------
// aggregation: h[c] = relu( selfc[c]*xw[c] + sum_in coef*xw[row] + bias )
// warp per node, float4 per lane (128 features). Pure gathers, no atomics.
// --------------------------------------------------------------------------
__global__ void k_agg(const float* __restrict__ bias, int n)
{
    int gw = (blockIdx.x * blockDim.x + threadIdx.x) >> 5;
    int lane = threadIdx.x & 31;
    if (gw >= n) return;

    const float4* x4 = (const float4*)g_xw;
    float4 acc = x4[(size_t)gw * 32 + lane];
    float sc = g_selfc[gw];
    acc.x *= sc; acc.y *= sc; acc.z *= sc; acc.w *= sc;

    int p  = g_off[gw];
    int p1 = g_off[gw + 1];
    for (; p + 1 < p1; p += 2) {
        int r0 = g_srow[p];
        int r1 = g_srow[p + 1];
        float c0 = g_scoef[p];
        float c1 = g_scoef[p + 1];
        float4 u0 = x4[(size_t)r0 * 32 + lane];
        float4 u1 = x4[(size_t)r1 * 32 + lane];
        acc.x += c0 * u0.x + c1 * u1.x;
        acc.y += c0 * u0.y + c1 * u1.y;
        acc.z += c0 * u0.z + c1 * u1.z;
        acc.w += c0 * u0.w + c1 * u1.w;
    }
    if (p < p1) {
        int r0 = g_srow[p];
        float c0 = g_scoef[p];
        float4 u0 = x4[(size_t)r0 * 32 + lane];
        acc.x += c0 * u0.x;
        acc.y += c0 * u0.y;
        acc.z += c0 * u0.z;
        acc.w += c0 * u0.w;
    }

    float4 bb = ((const float4*)bias)[lane];
    float4 o;
    o.x = fmaxf(acc.x + bb.x, 0.0f);
    o.y = fmaxf(acc.y + bb.y, 0.0f);
    o.z = fmaxf(acc.z + bb.z, 0.0f);
    o.w = fmaxf(acc.w + bb.w, 0.0f);
    ((float4*)g_h)[(size_t)gw * 32 + lane] = o;
}

// --------------------------------------------------------------------------
// pooling: batch is sorted -> contiguous node range per graph, no atomics
// --------------------------------------------------------------------------
__global__ void k_bounds(int n, int G)
{
    int i = blockIdx.x * blockDim.x + threadIdx.x;
    if (i >= n) return;
    int b  = g_batch[i];
    int bp = (i == 0) ? -1 : g_batch[i - 1];
    for (int g = bp + 1; g <= b; g++) g_gstart[g] = i;
    if (i == n - 1) {
        for (int g = b + 1; g <= G; g++) g_gstart[g] = n;
    }
}

__global__ void k_pool(int G)
{
    int g = blockIdx.x;     // one block per graph
    int f = threadIdx.x;    // feature
    int s = g_gstart[g];
    int t = g_gstart[g + 1];
    float acc = 0.0f;
    for (int i = s; i < t; i++) acc += g_h[(size_t)i * HD + f];
    float c = (float)(t - s);
    g_pool[g * HD + f] = acc / fmaxf(c, 1.0f);
}

__global__ void k_final(const float* __restrict__ Wl, const float* __restrict__ bl,
                        float* __restrict__ out, int G)
{
    int idx = blockIdx.x * blockDim.x + threadIdx.x;
    if (idx >= G * 2) return;
    int g = idx >> 1;
    int o = idx & 1;
    float s = 0.0f;
#pragma unroll 8
    for (int hh = 0; hh < HD; hh++) s += g_pool[g * HD + hh] * Wl[hh * 2 + o];
    out[idx] = s + bl[o];
}

// --------------------------------------------------------------------------
static inline int ceil_div_i(int a, int b) { return (a + b - 1) / b; }

extern "C" void kernel_launch(void* const* d_in, const int* in_sizes, int n_in,
                              void* d_out, int out_size)
{
    (void)n_in;
    const float* x  = (const float*)d_in[0];
    const void*  ei = d_in[1];
    const float* ew = (const float*)d_in[2];
    const void*  bt = d_in[3];
    const float* W1 = (const float*)d_in[4];
    const float* b1 = (const float*)d_in[5];
    const float* W2 = (const float*)d_in[6];
    const float* b2 = (const float*)d_in[7];
    const float* Wl = (const float*)d_in[8];
    const float* bl = (const float*)d_in[9];
    float* out = (float*)d_out;

    int n = in_sizes[0] / HD;   // nodes
    int e = in_sizes[2];        // edges (edge_weight element count, dtype-safe)
    int G = out_size / 2;       // graphs

    k_detect<<<1, 1>>>((const int*)ei, (const int*)bt, n);
    k_convert_edges<<<ceil_div_i(e, 256), 256>>>(ei, e);
    k_convert_batch<<<ceil_div_i(n, 256), 256>>>(bt, n);

    k_init<<<ceil_div_i(n, 256), 256>>>(n);
    k_edge_accum<<<ceil_div_i(e, 256), 256>>>(ew, e);
    k_dis<<<ceil_div_i(n, 256), 256>>>(n);

    int nb = ceil_div_i(n, 1024);
    k_scan1<<<nb, 1024>>>(n);
    k_scan2<<<1, 1024>>>(nb);
    k_scan3<<<ceil_div_i(n, 256), 256>>>(n, e);
    k_scatter<<<ceil_div_i(e, 256), 256>>>(ew, e);

    int gemm_blocks = ceil_div_i(n, 128);
    int agg_blocks  = ceil_div_i(n, 8);   // 8 warps (nodes) per 256-thread block

    // layer 1
    k_gemm<<<gemm_blocks, 256>>>(x, W1, 0, n);
    k_agg<<<agg_blocks, 256>>>(b1, n);
    // layer 2
    k_gemm<<<gemm_blocks, 256>>>(x, W2, 1, n);
    k_agg<<<agg_blocks, 256>>>(b2, n);

    // pooling + classifier
    k_bounds<<<ceil_div_i(n, 256), 256>>>(n, G);
    k_pool<<<G, HD>>>(G);
    k_final<<<ceil_div_i(G * 2, 128), 128>>>(Wl, bl, out, G);
}

// round 5
// speedup vs baseline: 1.0567x; 1.0567x over previous
#include <cuda_runtime.h>
#include <stdint.h>

// GCN graph classifier: 2x (GCNConv + ReLU) -> global_mean_pool -> Linear
// N=100k nodes, E=1.6M edges, H=128, G=512, OUT=2.
//
// R5 changes vs R4 (473us):
//  - forked capture stream: GEMM1 (depends only on x) overlaps the whole
//    CSR/preprocessing chain (fork/join via events; sequential fallback)
//  - prep kernels fused 11->6; dtype detect is a per-block ballot preamble
//  - CSR entries interleaved as int2{row, coef_bits}: one 8B load per edge
//  - GEMM: double-buffered smem, 1 sync/iter, clamped-row loads
//  - pool + bounds(binary search) + final linear fused into one kernel

#define HD   128
#define NMAX 100352
#define EMAX 1605632

__device__ __align__(16) float g_deg[NMAX];      // weighted in-degree (+1 self)
__device__ __align__(16) float g_dis[NMAX];      // rsqrt(deg)
__device__ __align__(16) int   g_row[EMAX];
__device__ __align__(16) int   g_col[EMAX];
__device__ __align__(16) int   g_batch[NMAX];
__device__ __align__(16) int   g_cnt[NMAX];
__device__ __align__(16) int   g_off[NMAX + 1];
__device__ __align__(16) int   g_cur[NMAX];
__device__ __align__(16) int   g_bsum[128];
__device__ __align__(16) int   g_bsumx[128];
__device__ __align__(16) int2  g_edge[EMAX];     // {src row, float coef bits}
__device__ __align__(16) float g_xw[(size_t)NMAX * HD];
__device__ __align__(16) float g_h[(size_t)NMAX * HD];

// ---------------------------------------------------------------------------
// per-block dtype detection (int64 arrays have zero hi-words at odd indices)
// ---------------------------------------------------------------------------
__device__ __forceinline__ int detect_ei64(const int* ei32)
{
    // words 1,3,..,63: hi halves of first 32 int64 values (0 if int64);
    // if int32 these are random node ids in [0,N) -> nonzero w.h.p.
    int lane = threadIdx.x & 31;
    int v = ei32[2 * lane + 1];
    return __all_sync(0xffffffffu, v == 0);
}

__device__ __forceinline__ int detect_b64(const int* b32, int n)
{
    // batch is sorted ascending to ~G-1: sample odd words near the end of the
    // first n 32-bit words (int32 -> large values; int64 -> hi halves = 0)
    int lane = threadIdx.x & 31;
    int base = (n > 64) ? ((n - 64) & ~1) : 0;
    int v = b32[base + 2 * lane + 1];
    return __all_sync(0xffffffffu, v == 0);
}

// ---------------------------------------------------------------------------
// prep1: convert edge_index + batch, init deg/cnt
// ---------------------------------------------------------------------------
__global__ void k_prep1(const void* __restrict__ ei, const void* __restrict__ bt,
                        int n, int e)
{
    __shared__ int s_ei64, s_b64;
    const int* ei32 = (const int*)ei;
    const int* bt32 = (const int*)bt;
    int tid = threadIdx.x;
    if (tid < 32) {
        int r = detect_ei64(ei32);
        if (tid == 0) s_ei64 = r;
    } else if (tid < 64) {
        int r = detect_b64(bt32, n);
        if (tid == 32) s_b64 = r;
    }
    __syncthreads();

    int i = blockIdx.x * blockDim.x + tid;
    if (i < e) {
        if (s_ei64) {
            const long long* p = (const long long*)ei;
            g_row[i] = (int)p[i];
            g_col[i] = (int)p[(size_t)e + i];
        } else {
            g_row[i] = ei32[i];
            g_col[i] = ei32[e + i];
        }
    }
    if (i < n) {
        g_deg[i] = 1.0f;   // self-loop weight
        g_cnt[i] = 0;
        g_batch[i] = s_b64 ? (int)((const long long*)bt)[i] : bt32[i];
    }
}

// histogram + weighted degree
__global__ void k_hist(const float* __restrict__ ew, int e)
{
    int i = blockIdx.x * blockDim.x + threadIdx.x;
    if (i >= e) return;
    int c = g_col[i];
    atomicAdd(&g_deg[c], ew[i]);
    atomicAdd(&g_cnt[c], 1);
}

// fused: blocks [0,nb) = within-block inclusive scan of cnt; blocks [nb,..) = rsqrt(deg)
__global__ void k_scan_dis(int n, int nb)
{
    if ((int)blockIdx.x < nb) {
        __shared__ int s[1024];
        int i = blockIdx.x * 1024 + threadIdx.x;
        int v = (i < n) ? g_cnt[i] : 0;
        s[threadIdx.x] = v;
        __syncthreads();
        for (int off = 1; off < 1024; off <<= 1) {
            int t = 0;
            if ((int)threadIdx.x >= off) t = s[threadIdx.x - off];
            __syncthreads();
            if ((int)threadIdx.x >= off) s[threadIdx.x] += t;
            __syncthreads();
        }
        if (i < n) g_off[i] = s[threadIdx.x];
        if (threadIdx.x == 1023) g_bsum[blockIdx.x] = s[1023];
    } else {
        int i = (blockIdx.x - nb) * 1024 + threadIdx.x;
        if (i < n) g_dis[i] = rsqrtf(g_deg[i]);   // deg >= 1
    }
}

__global__ void k_scan2(int nb)
{
    __shared__ int s[1024];
    int t = threadIdx.x;
    int v = (t < nb) ? g_bsum[t] : 0;
    s[t] = v;
    __syncthreads();
    for (int off = 1; off < 1024; off <<= 1) {
        int u = 0;
        if (t >= off) u = s[t - off];
        __syncthreads();
        if (t >= off) s[t] += u;
        __syncthreads();
    }
    if (t < nb) g_bsumx[t] = s[t] - v;
}

__global__ void k_scan3(int n, int e)
{
    int i = blockIdx.x * blockDim.x + threadIdx.x;
    if (i < n) {
        int ex = g_off[i] - g_cnt[i] + g_bsumx[i >> 10];
        g_off[i] = ex;
        g_cur[i] = ex;
    }
    if (i == 0) g_off[n] = e;
}

__global__ void k_scatter(const float* __restrict__ ew, int e)
{
    int i = blockIdx.x * blockDim.x + threadIdx.x;
    if (i >= e) return;
    int r = g_row[i];
    int c = g_col[i];
    float coef = g_dis[r] * ew[i] * g_dis[c];
    int slot = atomicAdd(&g_cur[c], 1);
    g_edge[slot] = make_int2(r, __float_as_int(coef));
}

// ---------------------------------------------------------------------------
// SGEMM: g_xw[n x 128] = A[n x 128] @ W[128 x 128]
// 128x128 tile, 8x8/thread, K-chunk 8, double-buffered smem, 1 sync/iter
// ---------------------------------------------------------------------------
__global__ void __launch_bounds__(256, 2) k_gemm(const float* __restrict__ Xin,
                                                 const float* __restrict__ W,
                                                 int useH, int n)
{
    __shared__ __align__(16) float As[2][8][128];
    __shared__ __align__(16) float Ws[2][8][128];

    const float* A = useH ? (const float*)g_h : Xin;
    float* C = g_xw;

    int tid = threadIdx.x;
    int tx = tid & 15;
    int ty = tid >> 4;
    int m0 = ty * 8;
    int n0 = tx * 8;
    int rowBase = blockIdx.x * 128;

    int lr = tid >> 1;                 // tile row 0..127
    int kp = (tid & 1) * 4;            // 0 or 4
    int arow = min(rowBase + lr, n - 1);   // clamp: OOB rows duplicate row n-1
    const float* aptr = A + (size_t)arow * HD + kp;
    int wk = (tid * 4) >> 7;
    int wn = (tid * 4) & 127;
    const float* wptr = W + (size_t)wk * HD + wn;

    // prologue: chunk 0 into buffer 0
    float4 av = *(const float4*)aptr;
    float4 wv = *(const float4*)wptr;
    As[0][kp + 0][lr] = av.x;
    As[0][kp + 1][lr] = av.y;
    As[0][kp + 2][lr] = av.z;
    As[0][kp + 3][lr] = av.w;
    *(float4*)&Ws[0][wk][wn] = wv;
    __syncthreads();

    float acc[8][8];
#pragma unroll
    for (int i = 0; i < 8; i++)
#pragma unroll
        for (int j = 0; j < 8; j++) acc[i][j] = 0.0f;

#pragma unroll
    for (int kc = 0; kc < 16; kc++) {
        int cur = kc & 1;
        int nxt = cur ^ 1;
        if (kc < 15) {
            av = *(const float4*)(aptr + (kc + 1) * 8);
            wv = *(const float4*)(wptr + (size_t)(kc + 1) * 8 * HD);
        }
#pragma unroll
        for (int k = 0; k < 8; k++) {
            float a[8], w[8];
            *(float4*)&a[0] = *(const float4*)&As[cur][k][m0];
            *(float4*)&a[4] = *(const float4*)&As[cur][k][m0 + 4];
            *(float4*)&w[0] = *(const float4*)&Ws[cur][k][n0];
            *(float4*)&w[4] = *(const float4*)&Ws[cur][k][n0 + 4];
#pragma unroll
            for (int i = 0; i < 8; i++)
#pragma unroll
                for (int j = 0; j < 8; j++)
                    acc[i][j] += a[i] * w[j];
        }
        if (kc < 15) {
            As[nxt][kp + 0][lr] = av.x;
            As[nxt][kp + 1][lr] = av.y;
            As[nxt][kp + 2][lr] = av.z;
            As[nxt][kp + 3][lr] = av.w;
            *(float4*)&Ws[nxt][wk][wn] = wv;
        }
        __syncthreads();
    }

#pragma unroll
    for (int i = 0; i < 8; i++) {
        int r = rowBase + m0 + i;
        if (r < n) {
            *(float4*)(C + (size_t)r * HD + n0) =
                make_float4(acc[i][0], acc[i][1], acc[i][2], acc[i][3]);
            *(float4*)(C + (size_t)r * HD + n0 + 4) =
                make_float4(acc[i][4], acc[i][5], acc[i][6], acc[i][7]);
        }
    }
}

// ---------------------------------------------------------------------------
// aggregation: h[c] = relu( dis[c]^2*xw[c] + sum coef*xw[src] + bias )
// warp per node, float4 lane slices, interleaved CSR records, no atomics
// ---------------------------------------------------------------------------
__global__ void k_agg(const float* __restrict__ bias, int n)
{
    int gw = (blockIdx.x * blockDim.x + threadIdx.x) >> 5;
    int lane = threadIdx.x & 31;
    if (gw >= n) return;

    const float4* x4 = (const float4*)g_xw;
    float sc = g_dis[gw];
    float4 acc = x4[(size_t)gw * 32 + lane];
    float s2 = sc * sc;
    acc.x *= s2; acc.y *= s2; acc.z *= s2; acc.w *= s2;

    int p  = g_off[gw];
    int p1 = g_off[gw + 1];
    for (; p + 3 < p1; p += 4) {
        int2 e0 = g_edge[p];
        int2 e1 = g_edge[p + 1];
        int2 e2 = g_edge[p + 2];
        int2 e3 = g_edge[p + 3];
        float4 u0 = x4[(size_t)e0.x * 32 + lane];
        float4 u1 = x4[(size_t)e1.x * 32 + lane];
        float4 u2 = x4[(size_t)e2.x * 32 + lane];
        float4 u3 = x4[(size_t)e3.x * 32 + lane];
        float c0 = __int_as_float(e0.y);
        float c1 = __int_as_float(e1.y);
        float c2 = __int_as_float(e2.y);
        float c3 = __int_as_float(e3.y);
        acc.x += c0 * u0.x + c1 * u1.x + c2 * u2.x + c3 * u3.x;
        acc.y += c0 * u0.y + c1 * u1.y + c2 * u2.y + c3 * u3.y;
        acc.z += c0 * u0.z + c1 * u1.z + c2 * u2.z + c3 * u3.z;
        acc.w += c0 * u0.w + c1 * u1.w + c2 * u2.w + c3 * u3.w;
    }
    for (; p < p1; p++) {
        int2 e0 = g_edge[p];
        float4 u0 = x4[(size_t)e0.x * 32 + lane];
        float c0 = __int_as_float(e0.y);
        acc.x += c0 * u0.x;
        acc.y += c0 * u0.y;
        acc.z += c0 * u0.z;
        acc.w += c0 * u0.w;
    }

    float4 bb = ((const float4*)bias)[lane];
    float4 o;
    o.x = fmaxf(acc.x + bb.x, 0.0f);
    o.y = fmaxf(acc.y + bb.y, 0.0f);
    o.z = fmaxf(acc.z + bb.z, 0.0f);
    o.w = fmaxf(acc.w + bb.w, 0.0f);
    ((float4*)g_h)[(size_t)gw * 32 + lane] = o;
}

// ---------------------------------------------------------------------------
// fused pooling + classifier: block per graph; bounds via binary search on
// the sorted batch array; mean-pool; 128->2 reduction in shared memory
// ---------------------------------------------------------------------------
__global__ void k_poolfinal(const float* __restrict__ Wl, const float* __restrict__ bl,
                            float* __restrict__ out, int n)
{
    int g = blockIdx.x;
    int f = threadIdx.x;
    __shared__ int sb[2];
    __shared__ float r0[128], r1[128];

    if (f < 2) {
        int target = g + f;
        int lo = 0, hi = n;
        while (lo < hi) {
            int mid = (lo + hi) >> 1;
            if (g_batch[mid] < target) lo = mid + 1; else hi = mid;
        }
        sb[f] = lo;
    }
    __syncthreads();
    int s = sb[0], t = sb[1];

    float acc = 0.0f;
    for (int i = s; i < t; i++) acc += g_h[(size_t)i * HD + f];
    float pooled = acc / fmaxf((float)(t - s), 1.0f);

    r0[f] = pooled * Wl[f * 2 + 0];
    r1[f] = pooled * Wl[f * 2 + 1];
    __syncthreads();
#pragma unroll
    for (int off = 64; off > 0; off >>= 1) {
        if (f < off) { r0[f] += r0[f + off]; r1[f] += r1[f + off]; }
        __syncthreads();
    }
    if (f == 0) {
        out[g * 2 + 0] = r0[0] + bl[0];
        out[g * 2 + 1] = r1[0] + bl[1];
    }
}

// ---------------------------------------------------------------------------
static inline int ceil_div_i(int a, int b) { return (a + b - 1) / b; }

extern "C" void kernel_launch(void* const* d_in, const int* in_sizes, int n_in,
                              void* d_out, int out_size)
{
    (void)n_in;
    const float* x  = (const float*)d_in[0];
    const void*  ei = d_in[1];
    const float* ew = (const float*)d_in[2];
    const void*  bt = d_in[3];
    const float* W1 = (const float*)d_in[4];
    const float* b1 = (const float*)d_in[5];
    const float* W2 = (const float*)d_in[6];
    const float* b2 = (const float*)d_in[7];
    const float* Wl = (const float*)d_in[8];
    const float* bl = (const float*)d_in[9];
    float* out = (float*)d_out;

    int n = in_sizes[0] / HD;   // nodes
    int e = in_sizes[2];        // edges (edge_weight count, dtype-independent)
    int G = out_size / 2;       // graphs

    int eb = ceil_div_i(e, 256);
    int nb = ceil_div_i(n, 1024);
    int gemm_blocks = ceil_div_i(n, 128);
    int agg_blocks  = ceil_div_i(n, 8);

    // Fork a side stream for GEMM1 (depends only on x) so the CSR build
    // chain overlaps it. Kernel_launch is called only a handful of times
    // (correctness + capture), so per-call stream/event creation is cheap.
    cudaStream_t s2 = 0;
    cudaEvent_t evA = 0, evB = 0;
    bool forked = false;
    if (cudaStreamCreateWithFlags(&s2, cudaStreamNonBlocking) == cudaSuccess &&
        cudaEventCreateWithFlags(&evA, cudaEventDisableTiming) == cudaSuccess &&
        cudaEventCreateWithFlags(&evB, cudaEventDisableTiming) == cudaSuccess) {
        if (cudaEventRecord(evA, 0) == cudaSuccess &&
            cudaStreamWaitEvent(s2, evA, 0) == cudaSuccess)
            forked = true;
    }

    // GEMM1 on side stream (or inline if fork unavailable)
    cudaStream_t gs = forked ? s2 : (cudaStream_t)0;
    k_gemm<<<gemm_blocks, 256, 0, gs>>>(x, W1, 0, n);
    if (forked) cudaEventRecord(evB, s2);

    // CSR build chain on the main stream
    k_prep1<<<eb, 256>>>(ei, bt, n, e);
    k_hist<<<eb, 256>>>(ew, e);
    k_scan_dis<<<nb + ceil_div_i(n, 1024), 1024>>>(n, nb);
    k_scan2<<<1, 1024>>>(nb);
    k_scan3<<<ceil_div_i(n, 256), 256>>>(n, e);
    k_scatter<<<eb, 256>>>(ew, e);

    if (forked) cudaStreamWaitEvent(0, evB, 0);

    // layer 1 aggregate, layer 2
    k_agg<<<agg_blocks, 256>>>(b1, n);
    k_gemm<<<gemm_blocks, 256>>>(x, W2, 1, n);
    k_agg<<<agg_blocks, 256>>>(b2, n);

    // pooling + classifier
    k_poolfinal<<<G, 128>>>(Wl, bl, out, n);
}